// round 11
// baseline (speedup 1.0000x reference)
#include <cuda_runtime.h>
#include <cstdint>

// ---------------- configuration ----------------
#define THREADS 128
#define NT0     32           // layer-0 tiles (K=1024, 32 k each)
#define NT_ALL  96           // + 64 layer-1 tiles (K=2048)
#define WTILE   16384        // 128 rows x 128B, XOR-swizzled tf32
#define ZHALF   8192         // 64 rows x 128B per batch

// dynamic smem byte offsets (112KB per CTA -> 2 CTAs/SM)
#define OFF_X   0            // 2 * 8192   x fp32 [32][64] per batch
#define OFF_H   16384        // 2 * 16384  h fp32 [64][64] per batch
#define OFF_W   49152        // 2 * WTILE  (double-buffered W tile)
#define OFF_Z   81920        // 2 * (2*ZHALF) (double-buffered z, both batches)
#define SMEM_TOTAL 114688

// pre-converted, pre-swizzled W: 96 tf32 tiles
__device__ __align__(16) unsigned char g_Wpre[96 * WTILE];

// ---------------- helpers ----------------
static __device__ __forceinline__ uint32_t smem_u32(const void* p) {
    return (uint32_t)__cvta_generic_to_shared(p);
}
static __device__ __forceinline__ void cpa16(uint32_t dst, const void* src) {
    asm volatile("cp.async.cg.shared.global [%0], [%1], 16;" :: "r"(dst), "l"(src));
}
static __device__ __forceinline__ void cp_commit() { asm volatile("cp.async.commit_group;"); }
template <int N>
static __device__ __forceinline__ void cp_wait() { asm volatile("cp.async.wait_group %0;" :: "n"(N)); }

static __device__ __forceinline__ void sts128(uint32_t a, uint32_t r0, uint32_t r1, uint32_t r2, uint32_t r3) {
    asm volatile("st.shared.v4.b32 [%0], {%1, %2, %3, %4};" :: "r"(a), "r"(r0), "r"(r1), "r"(r2), "r"(r3));
}
static __device__ __forceinline__ void ldmx4(uint32_t* r, uint32_t a) {
    asm volatile("ldmatrix.sync.aligned.m8n8.x4.shared.b16 {%0,%1,%2,%3}, [%4];"
        : "=r"(r[0]), "=r"(r[1]), "=r"(r[2]), "=r"(r[3]) : "r"(a));
}
static __device__ __forceinline__ uint32_t f2tf32(float f) {
    uint32_t r; asm("cvt.rna.tf32.f32 %0, %1;" : "=r"(r) : "f"(f)); return r;
}
// m16n8k8 row.col tf32 -> f32, D += A*B (register-pure)
static __device__ __forceinline__ void mma_tf32(float* c, const uint32_t* a, const uint32_t* b) {
    asm("mma.sync.aligned.m16n8k8.row.col.f32.tf32.tf32.f32 "
        "{%0,%1,%2,%3}, {%4,%5,%6,%7}, {%8,%9}, {%0,%1,%2,%3};"
        : "+f"(c[0]), "+f"(c[1]), "+f"(c[2]), "+f"(c[3])
        : "r"(a[0]), "r"(a[1]), "r"(a[2]), "r"(a[3]), "r"(b[0]), "r"(b[1]));
}

// ---------------- prep: round W to tf32, XOR-swizzled 32-k tiles ----------------
__global__ void prep_kernel(const float* __restrict__ W0, const float* __restrict__ W1) {
    int idx = blockIdx.x * 256 + threadIdx.x;      // 0..393215
    float w; int o, k; size_t base;
    if (idx < 131072) { o = idx >> 10; k = idx & 1023; w = W0[idx]; base = (size_t)(k >> 5) * WTILE; }
    else { int j = idx - 131072; o = j >> 11; k = j & 2047; w = W1[j]; base = (size_t)(32 + (k >> 5)) * WTILE; }
    uint32_t c = (uint32_t)((k >> 2) & 7);         // 16B chunk within row
    size_t off = base + (size_t)o * 128 + (size_t)(((c ^ (o & 7)) << 4) + (k & 3) * 4);
    *(uint32_t*)(g_Wpre + off) = f2tf32(w);
}

// ---------------- main kernel ----------------
__global__ __launch_bounds__(THREADS, 2)
void cin_mma_kernel(const float* __restrict__ xg,
                    const float* __restrict__ b0g,
                    const float* __restrict__ b1g,
                    float* __restrict__ out)
{
    extern __shared__ __align__(256) unsigned char smem[];
    const uint32_t sb = smem_u32(smem);
    const int tid  = threadIdx.x;
    const int wid  = tid >> 5;
    const int lane = tid & 31;
    const int lr   = lane >> 2;
    const int lc   = lane & 3;

    const int bz = wid >> 1;        // warp's batch (0/1)
    const int oh = wid & 1;         // warp o-half -> o base oh*64

    // swizzled ldmatrix addressing
    const uint32_t l7  = (uint32_t)(lane & 7);
    const uint32_t aHi = (uint32_t)((lane >> 4) & 1);
    const uint32_t bHi = (uint32_t)((lane >> 3) & 1);
    const uint32_t aRowOff = (uint32_t)((oh * 64 + (lane & 15)) * 128);
    const uint32_t bRowOff = (uint32_t)(((lane & 7) + ((lane & 16) >> 1)) * 128);

    float* xs = (float*)(smem + OFF_X);
    float* hs = (float*)(smem + OFF_H);

    const int bbase = blockIdx.x * 2;

    // initial loads: x (16KB) + W tile 0 (16KB), 8+8 chunks/thread
    {
        const char* src = (const char*)(xg + (size_t)bbase * 2048);
        #pragma unroll
        for (int r = 0; r < 8; r++)
            cpa16(sb + OFF_X + (uint32_t)(r * THREADS + tid) * 16, src + (size_t)(r * THREADS + tid) * 16);
        #pragma unroll
        for (int r = 0; r < 8; r++)
            cpa16(sb + OFF_W + (uint32_t)(r * THREADS + tid) * 16, g_Wpre + (size_t)(r * THREADS + tid) * 16);
        cp_commit();
    }

    // z producer mapping: thread -> (batch bzt, d), all 32 m
    const int d   = tid & 63;
    const int bzt = tid >> 6;
    const uint32_t d7 = (uint32_t)(d & 7);

    cp_wait<0>();
    __syncthreads();

    // register-cached x values (loop-invariant across both layers)
    float xmc[32];
    #pragma unroll
    for (int j = 0; j < 32; j++) xmc[j] = xs[bzt * 2048 + j * 64 + d];

    // build z tile j (both batches), buffer j&1, xh passed in a register.
    // Chunked (4 values -> sts128) to keep transient register count low.
    auto build_z = [&](int j, float xh) {
        const uint32_t zb = sb + OFF_Z + (uint32_t)(j & 1) * (2 * ZHALF) + (uint32_t)bzt * ZHALF
                          + (uint32_t)(d * 128);
        #pragma unroll
        for (int c4 = 0; c4 < 8; c4++) {
            uint32_t t0 = f2tf32(xh * xmc[4 * c4 + 0]);
            uint32_t t1 = f2tf32(xh * xmc[4 * c4 + 1]);
            uint32_t t2 = f2tf32(xh * xmc[4 * c4 + 2]);
            uint32_t t3 = f2tf32(xh * xmc[4 * c4 + 3]);
            sts128(zb + (((uint32_t)c4 ^ d7) << 4), t0, t1, t2, t3);
        }
    };

    float acc[4][8][4];             // [mi][nj][q] — statically indexed, 128 regs
    #pragma unroll
    for (int mi = 0; mi < 4; mi++)
        #pragma unroll
        for (int nj = 0; nj < 8; nj++)
            #pragma unroll
            for (int q = 0; q < 4; q++) acc[mi][nj][q] = 0.0f;

    build_z(0, xs[bzt * 2048 + d]);                 // tile 0 (h-row 0)
    float xh_next = xs[bzt * 2048 + 64 + d];        // xh for tile 1

    for (int g = 0; g < NT_ALL; g++) {
        if (g > 0) cp_wait<0>();          // W(g) resident
        __syncthreads();                  // z(g) visible; z(g-1) readers done

        const uint32_t wbuf = sb + OFF_W + (uint32_t)(g & 1) * WTILE;
        const uint32_t aA   = wbuf + aRowOff;
        const uint32_t bB   = sb + OFF_Z + (uint32_t)(g & 1) * (2 * ZHALF)
                            + (uint32_t)bz * ZHALF + bRowOff;

        // ---- peel ks=0 fragment loads: feed the tensor pipe ASAP
        uint32_t A[4][4], B[4][4];
        {
            const uint32_t swA = (aHi ^ l7) << 4;
            const uint32_t swB = (bHi ^ l7) << 4;
            #pragma unroll
            for (int t4 = 0; t4 < 4; t4++) ldmx4(A[t4], aA + (uint32_t)(t4 * 2048) + swA);
            #pragma unroll
            for (int t4 = 0; t4 < 4; t4++) ldmx4(B[t4], bB + (uint32_t)(t4 * 2048) + swB);
        }

        // build z(g+1) (overlaps with ks0 MMA stream below)
        if (g + 1 < NT_ALL && g != NT0 - 1) build_z(g + 1, xh_next);

        // prefetch xh for tile g+2 (layer-transition tiles handled in epilogue)
        {
            const int t = g + 2;
            if (t < NT0)            xh_next = xs[bzt * 2048 + t * 64 + d];
            else if (g >= NT0 && t < NT_ALL)
                                    xh_next = hs[bzt * 4096 + (t - NT0) * 64 + d];
        }

        if (g + 1 < NT_ALL) {             // prefetch next W tile (8 chunks/thread)
            const unsigned char* src = g_Wpre + (size_t)(g + 1) * WTILE;
            uint32_t dst = sb + OFF_W + (uint32_t)((g + 1) & 1) * WTILE;
            #pragma unroll
            for (int r = 0; r < 8; r++)
                cpa16(dst + (uint32_t)(r * THREADS + tid) * 16, src + (size_t)(r * THREADS + tid) * 16);
            cp_commit();
        }

        // ---- ks=0 MMAs (frags already in flight)
        #pragma unroll
        for (int mi = 0; mi < 4; mi++)
            #pragma unroll
            for (int t4 = 0; t4 < 4; t4++) {
                mma_tf32(acc[mi][2*t4],     A[mi], B[t4]);
                mma_tf32(acc[mi][2*t4 + 1], A[mi], B[t4] + 2);
            }

        // ---- ks=1..3
        #pragma unroll
        for (uint32_t ks = 1; ks < 4; ks++) {
            const uint32_t swA = (((ks << 1) | aHi) ^ l7) << 4;
            const uint32_t swB = (((ks << 1) | bHi) ^ l7) << 4;
            #pragma unroll
            for (int t4 = 0; t4 < 4; t4++) ldmx4(A[t4], aA + (uint32_t)(t4 * 2048) + swA);
            #pragma unroll
            for (int t4 = 0; t4 < 4; t4++) ldmx4(B[t4], bB + (uint32_t)(t4 * 2048) + swB);
            #pragma unroll
            for (int mi = 0; mi < 4; mi++)
                #pragma unroll
                for (int t4 = 0; t4 < 4; t4++) {
                    mma_tf32(acc[mi][2*t4],     A[mi], B[t4]);
                    mma_tf32(acc[mi][2*t4 + 1], A[mi], B[t4] + 2);
                }
        }

        if (g == NT0 - 1) {
            // ======== layer-0 epilogue ========
            __syncthreads();              // all layer-0 MMA smem reads done
            #pragma unroll
            for (int mi = 0; mi < 4; mi++) {
                const int o = oh * 64 + mi * 16 + lr;
                const float bias0 = b0g[o], bias1 = b0g[o + 8];
                if (oh == 0) {            // rows 0..63 -> h
                    float* h0 = hs + bz * 4096 + o * 64;
                    float* h1 = h0 + 8 * 64;
                    #pragma unroll
                    for (int nj = 0; nj < 8; nj++) {
                        const int dd = nj * 8 + 2 * lc;
                        h0[dd]     = fmaxf(acc[mi][nj][0] + bias0, 0.0f);
                        h0[dd + 1] = fmaxf(acc[mi][nj][1] + bias0, 0.0f);
                        h1[dd]     = fmaxf(acc[mi][nj][2] + bias1, 0.0f);
                        h1[dd + 1] = fmaxf(acc[mi][nj][3] + bias1, 0.0f);
                    }
                } else {                  // rows 64..127 -> out rows 0..63
                    float s0 = 0.0f, s1 = 0.0f;
                    #pragma unroll
                    for (int nj = 0; nj < 8; nj++) {
                        s0 += fmaxf(acc[mi][nj][0] + bias0, 0.0f)
                            + fmaxf(acc[mi][nj][1] + bias0, 0.0f);
                        s1 += fmaxf(acc[mi][nj][2] + bias1, 0.0f)
                            + fmaxf(acc[mi][nj][3] + bias1, 0.0f);
                    }
                    s0 += __shfl_xor_sync(0xffffffffu, s0, 1);
                    s0 += __shfl_xor_sync(0xffffffffu, s0, 2);
                    s1 += __shfl_xor_sync(0xffffffffu, s1, 1);
                    s1 += __shfl_xor_sync(0xffffffffu, s1, 2);
                    if (lc == 0) {
                        out[(size_t)(bbase + bz) * 192 + (o - 64)]     = s0;
                        out[(size_t)(bbase + bz) * 192 + (o - 64) + 8] = s1;
                    }
                }
            }
            #pragma unroll
            for (int mi = 0; mi < 4; mi++)
                #pragma unroll
                for (int nj = 0; nj < 8; nj++)
                    #pragma unroll
                    for (int q = 0; q < 4; q++) acc[mi][nj][q] = 0.0f;
            __syncthreads();              // h complete before z(32) reads it
            build_z(NT0, hs[bzt * 4096 + d]);            // tile NT0 (h-row 0)
            xh_next = hs[bzt * 4096 + 64 + d];           // xh for tile NT0+1
        }
    }

    // ======== layer-1 epilogue: out rows 64..191, direct ========
    #pragma unroll
    for (int mi = 0; mi < 4; mi++) {
        const int o = oh * 64 + mi * 16 + lr;
        const float bias0 = b1g[o], bias1 = b1g[o + 8];
        float s0 = 0.0f, s1 = 0.0f;
        #pragma unroll
        for (int nj = 0; nj < 8; nj++) {
            s0 += fmaxf(acc[mi][nj][0] + bias0, 0.0f)
                + fmaxf(acc[mi][nj][1] + bias0, 0.0f);
            s1 += fmaxf(acc[mi][nj][2] + bias1, 0.0f)
                + fmaxf(acc[mi][nj][3] + bias1, 0.0f);
        }
        s0 += __shfl_xor_sync(0xffffffffu, s0, 1);
        s0 += __shfl_xor_sync(0xffffffffu, s0, 2);
        s1 += __shfl_xor_sync(0xffffffffu, s1, 1);
        s1 += __shfl_xor_sync(0xffffffffu, s1, 2);
        if (lc == 0) {
            out[(size_t)(bbase + bz) * 192 + 64 + o]     = s0;
            out[(size_t)(bbase + bz) * 192 + 64 + o + 8] = s1;
        }
    }
}

// ---------------- launch ----------------
extern "C" void kernel_launch(void* const* d_in, const int* in_sizes, int n_in,
                              void* d_out, int out_size) {
    const float* xg = (const float*)d_in[0];   // (2048,32,64)
    const float* W0 = (const float*)d_in[1];   // (128,1024)
    const float* b0 = (const float*)d_in[2];   // (128)
    const float* W1 = (const float*)d_in[3];   // (128,2048)
    const float* b1 = (const float*)d_in[4];   // (128)
    float* out = (float*)d_out;                // (2048,192)

    prep_kernel<<<1536, 256>>>(W0, W1);

    cudaFuncSetAttribute((const void*)cin_mma_kernel,
                         cudaFuncAttributeMaxDynamicSharedMemorySize, SMEM_TOTAL);
    cin_mma_kernel<<<1024, THREADS, SMEM_TOTAL>>>(xg, b0, b1, out);
}